// round 16
// baseline (speedup 1.0000x reference)
#include <cuda_runtime.h>
#include <cuda_fp16.h>
#include <cstdint>

#define BATCH 4096
#define NE    64
#define EPSV  1e-5f

// ===================== device scratch (no runtime alloc) ====================
__device__ __align__(16) float g_buf0[BATCH * 256];
__device__ __align__(16) float g_buf1[BATCH * 256];
__device__ __align__(16) float g_buf2[BATCH * 256];
__device__ __align__(16) float g_w   [BATCH * NE];
__device__ float g_sum;

// fp16 activations: expert path (single) + MNet ping-pong (hi/lo)
__device__ __align__(16) __half g_Zf  [BATCH * 256];
__device__ __align__(16) __half g_Zm  [BATCH * 256];
__device__ __align__(16) __half g_Zml [BATCH * 256];
__device__ __align__(16) __half g_Zm2 [BATCH * 256];
__device__ __align__(16) __half g_Zm2l[BATCH * 256];

// fp16 expert weights: enc0(1M) enc1(4M) dec0(4M) dec1(1M)
#define OFF_ENC0 0
#define OFF_ENC1 1048576
#define OFF_DEC0 5242880
#define OFF_DEC1 9437184
#define W_TOTAL  10485760
__device__ __align__(16) __half g_Wf[W_TOTAL];

// fp16 MNet weights hi/lo: W1(256x128) W2(128x256) W3(64x128)
#define OFF_MW1 0
#define OFF_MW2 32768
#define OFF_MW3 65536
__device__ __align__(16) __half g_Wm [73728];
__device__ __align__(16) __half g_Wml[73728];

// ===================== PTX helpers (base sm_103 target only) ===============
__device__ __forceinline__ uint32_t smem_u32(const void* p) {
    uint32_t a;
    asm("{ .reg .u64 t; cvta.to.shared.u64 t, %1; cvt.u32.u64 %0, t; }"
        : "=r"(a) : "l"(p));
    return a;
}

#define LDSM4(r, a) \
    asm volatile("ldmatrix.sync.aligned.m8n8.x4.shared.b16 {%0,%1,%2,%3}, [%4];" \
        : "=r"((r)[0]), "=r"((r)[1]), "=r"((r)[2]), "=r"((r)[3]) : "r"(a))

#define MMA16816H(d, a, b0v, b1v) \
    asm volatile("mma.sync.aligned.m16n8k16.row.col.f32.f16.f16.f32 " \
        "{%0,%1,%2,%3}, {%4,%5,%6,%7}, {%8,%9}, {%0,%1,%2,%3};" \
        : "+f"((d)[0]), "+f"((d)[1]), "+f"((d)[2]), "+f"((d)[3]) \
        : "r"((a)[0]), "r"((a)[1]), "r"((a)[2]), "r"((a)[3]), "r"(b0v), "r"(b1v))

#define CP_ASYNC16(dst, src) \
    asm volatile("cp.async.cg.shared.global [%0], [%1], 16;" :: "r"(dst), "l"(src))
#define CP_COMMIT() asm volatile("cp.async.commit_group;" ::: "memory")
#define CP_WAIT1()  asm volatile("cp.async.wait_group 1;" ::: "memory")
#define CP_WAIT0()  asm volatile("cp.async.wait_group 0;" ::: "memory")

// ============ convert fp32 -> fp16 (8 elems, single) =======================
__device__ __forceinline__ uint4 cvt8(const float* __restrict__ src8) {
    float4 v0 = reinterpret_cast<const float4*>(src8)[0];
    float4 v1 = reinterpret_cast<const float4*>(src8)[1];
    __half2 h0 = __floats2half2_rn(v0.x, v0.y);
    __half2 h1 = __floats2half2_rn(v0.z, v0.w);
    __half2 h2 = __floats2half2_rn(v1.x, v1.y);
    __half2 h3 = __floats2half2_rn(v1.z, v1.w);
    return make_uint4(*reinterpret_cast<uint32_t*>(&h0),
                      *reinterpret_cast<uint32_t*>(&h1),
                      *reinterpret_cast<uint32_t*>(&h2),
                      *reinterpret_cast<uint32_t*>(&h3));
}

// ============ split fp32 -> fp16 hi/lo (8 elems) ===========================
__device__ __forceinline__ void split8(const float* __restrict__ src8,
                                       uint4& hv, uint4& lv) {
    float4 v0 = reinterpret_cast<const float4*>(src8)[0];
    float4 v1 = reinterpret_cast<const float4*>(src8)[1];
    float f[8] = {v0.x, v0.y, v0.z, v0.w, v1.x, v1.y, v1.z, v1.w};
    uint32_t hw[4], lw[4];
    #pragma unroll
    for (int j = 0; j < 4; ++j) {
        __half2 h2 = __floats2half2_rn(f[2*j], f[2*j+1]);
        float q0 = f[2*j]   - __low2float(h2);
        float q1 = f[2*j+1] - __high2float(h2);
        __half2 l2 = __floats2half2_rn(q0, q1);
        hw[j] = *reinterpret_cast<uint32_t*>(&h2);
        lw[j] = *reinterpret_cast<uint32_t*>(&l2);
    }
    hv = make_uint4(hw[0], hw[1], hw[2], hw[3]);
    lv = make_uint4(lw[0], lw[1], lw[2], lw[3]);
}

// ---- all weights + x0 (single) and mW1/2/3 + m0 (hi/lo) in ONE kernel -----
#define N8_0 (OFF_ENC1 / 8)
#define N8_1 (OFF_DEC0 / 8)
#define N8_2 (OFF_DEC1 / 8)
#define N8_3 (W_TOTAL / 8)
#define N8_4 (N8_3 + BATCH * 64 / 8)            // x0
#define N8_5 (N8_4 + 32768 / 8)                 // mW1
#define N8_6 (N8_5 + 32768 / 8)                 // mW2
#define N8_7 (N8_6 + 8192 / 8)                  // mW3
#define N8_8 (N8_7 + BATCH * 128 / 8)           // m0 -> 1418240 total
__global__ __launch_bounds__(256)
void cvt_all_kernel(const float* __restrict__ W0, const float* __restrict__ W1,
                    const float* __restrict__ W2, const float* __restrict__ W3,
                    const float* __restrict__ X0,
                    const float* __restrict__ MW1, const float* __restrict__ MW2,
                    const float* __restrict__ MW3, const float* __restrict__ M0,
                    __half* __restrict__ Wf, __half* __restrict__ Zf,
                    __half* __restrict__ WmH, __half* __restrict__ WmL,
                    __half* __restrict__ ZmH, __half* __restrict__ ZmL) {
    int i = blockIdx.x * 256 + threadIdx.x;
    if (i < N8_4) {
        // single-fp16 path (expert weights + x0)
        const float* src; int base; __half* dst; int di;
        if      (i < N8_0) { src = W0; base = 0;    dst = Wf; di = i; }
        else if (i < N8_1) { src = W1; base = N8_0; dst = Wf; di = i; }
        else if (i < N8_2) { src = W2; base = N8_1; dst = Wf; di = i; }
        else if (i < N8_3) { src = W3; base = N8_2; dst = Wf; di = i; }
        else               { src = X0; base = N8_3; dst = Zf; di = i - N8_3; }
        reinterpret_cast<uint4*>(dst)[i < N8_3 ? i : di] =
            cvt8(src + (size_t)(i - base) * 8);
    } else {
        // hi/lo path (MNet weights + m0)
        const float* src; int base; __half *dh, *dl; int di;
        if      (i < N8_5) { src = MW1; base = N8_4; dh = WmH; dl = WmL; di = i - N8_4 + OFF_MW1 / 8; }
        else if (i < N8_6) { src = MW2; base = N8_5; dh = WmH; dl = WmL; di = i - N8_5 + OFF_MW2 / 8; }
        else if (i < N8_7) { src = MW3; base = N8_6; dh = WmH; dl = WmL; di = i - N8_6 + OFF_MW3 / 8; }
        else               { src = M0;  base = N8_7; dh = ZmH; dl = ZmL; di = i - N8_7; }
        uint4 hv, lv;
        split8(src + (size_t)(i - base) * 8, hv, lv);
        reinterpret_cast<uint4*>(dh)[di] = hv;
        reinterpret_cast<uint4*>(dl)[di] = lv;
    }
}

// ==== BN + PReLU in place + accumulate global sum (MNet layer 3 -> w) ======
__global__ __launch_bounds__(256)
void bn_prelu_wsum_kernel(float* __restrict__ X, const float* __restrict__ g,
                          const float* __restrict__ be, const float* __restrict__ aP,
                          int C) {
    __shared__ float s1[256], s2[256];
    int tid = threadIdx.x;
    int col = blockIdx.x * 2 + (tid & 1);
    int r0  = tid >> 1;
    float sum = 0.f, sq = 0.f;
    for (int r = r0; r < BATCH; r += 128) {
        float v = X[(size_t)r * C + col];
        sum += v; sq += v * v;
    }
    s1[tid] = sum; s2[tid] = sq;
    __syncthreads();
    #pragma unroll
    for (int off = 128; off >= 2; off >>= 1) {
        if (tid < off) { s1[tid] += s1[tid + off]; s2[tid] += s2[tid + off]; }
        __syncthreads();
    }
    float mean = s1[tid & 1] * (1.f / BATCH);
    float var  = s2[tid & 1] * (1.f / BATCH) - mean * mean;
    float sc   = g[col] * rsqrtf(var + EPSV);
    float sh   = be[col] - mean * sc;
    float a    = aP[0];
    float wsum = 0.f;
    for (int r = r0; r < BATCH; r += 128) {
        float v = X[(size_t)r * C + col] * sc + sh;
        v = (v >= 0.f) ? v : a * v;
        X[(size_t)r * C + col] = v;
        wsum += v;
    }
    __syncthreads();
    s1[tid] = wsum;
    __syncthreads();
    #pragma unroll
    for (int off = 128; off; off >>= 1) {
        if (tid < off) s1[tid] += s1[tid + off];
        __syncthreads();
    }
    if (tid == 0) atomicAdd(&g_sum, s1[0]);
}

// ====== BN + PReLU fused with fp16 convert (expert path, single) ===========
__global__ __launch_bounds__(256)
void bn_prelu_h_kernel(const float* __restrict__ X, const float* __restrict__ g,
                       const float* __restrict__ be, const float* __restrict__ aP,
                       int C, __half* __restrict__ Zf) {
    __shared__ float s1[256], s2[256];
    int tid = threadIdx.x;
    int col = blockIdx.x * 2 + (tid & 1);
    int r0  = tid >> 1;
    float sum = 0.f, sq = 0.f;
    for (int r = r0; r < BATCH; r += 128) {
        float v = X[(size_t)r * C + col];
        sum += v; sq += v * v;
    }
    s1[tid] = sum; s2[tid] = sq;
    __syncthreads();
    #pragma unroll
    for (int off = 128; off >= 2; off >>= 1) {
        if (tid < off) { s1[tid] += s1[tid + off]; s2[tid] += s2[tid + off]; }
        __syncthreads();
    }
    float mean = s1[tid & 1] * (1.f / BATCH);
    float var  = s2[tid & 1] * (1.f / BATCH) - mean * mean;
    float sc   = g[col] * rsqrtf(var + EPSV);
    float sh   = be[col] - mean * sc;
    float a    = aP[0];
    for (int r = r0; r < BATCH; r += 128) {
        float v = X[(size_t)r * C + col] * sc + sh;
        v = (v >= 0.f) ? v : a * v;
        Zf[(size_t)r * C + col] = __float2half_rn(v);
    }
}

// ====== BN + PReLU fused with fp16 HI/LO split (MNet path) =================
__global__ __launch_bounds__(256)
void bn_prelu_hl_kernel(const float* __restrict__ X, const float* __restrict__ g,
                        const float* __restrict__ be, const float* __restrict__ aP,
                        int C, __half* __restrict__ Zh, __half* __restrict__ Zl) {
    __shared__ float s1[256], s2[256];
    int tid = threadIdx.x;
    int col = blockIdx.x * 2 + (tid & 1);
    int r0  = tid >> 1;
    float sum = 0.f, sq = 0.f;
    for (int r = r0; r < BATCH; r += 128) {
        float v = X[(size_t)r * C + col];
        sum += v; sq += v * v;
    }
    s1[tid] = sum; s2[tid] = sq;
    __syncthreads();
    #pragma unroll
    for (int off = 128; off >= 2; off >>= 1) {
        if (tid < off) { s1[tid] += s1[tid + off]; s2[tid] += s2[tid + off]; }
        __syncthreads();
    }
    float mean = s1[tid & 1] * (1.f / BATCH);
    float var  = s2[tid & 1] * (1.f / BATCH) - mean * mean;
    float sc   = g[col] * rsqrtf(var + EPSV);
    float sh   = be[col] - mean * sc;
    float a    = aP[0];
    for (int r = r0; r < BATCH; r += 128) {
        float v = X[(size_t)r * C + col] * sc + sh;
        v = (v >= 0.f) ? v : a * v;
        __half h = __float2half_rn(v);
        Zh[(size_t)r * C + col] = h;
        Zl[(size_t)r * C + col] = __float2half_rn(v - __half2float(h));
    }
}

// ========= dense fp16 tensor GEMM, 3-product hi/lo split (MNet) ============
// z=0: Ah.Wh  z=1: Al.Wh  z=2: Ah.Wl ; atomicAdd into zeroed out.
template<int KDIM, int BN>
__global__ __launch_bounds__(256, 1)
void dense_mma_kernel(const __half* __restrict__ Ah, const __half* __restrict__ Al,
                      const __half* __restrict__ Wh, const __half* __restrict__ Wl,
                      float* __restrict__ out, int N) {
    constexpr int RS    = 144;
    constexpr int Ao    = 0;
    constexpr int Bo    = 128 * RS;
    constexpr int STAGE = (128 + BN) * RS;
    constexpr int NC    = KDIM / 64;
    constexpr int P     = BN / 32;
    constexpr int NT    = BN / 16;

    extern __shared__ char smem[];
    uint32_t sb = smem_u32(smem);

    int tid  = threadIdx.x;
    int lane = tid & 31, wid = tid >> 5;
    int wy = wid >> 1, wx = wid & 1;
    int m0 = blockIdx.y * 128;
    int n0 = blockIdx.x * BN;
    int bz = blockIdx.z;
    const __half* A = (bz == 1) ? Al : Ah;
    const __half* W = (bz == 2) ? Wl : Wh;

    auto load_chunk = [&](int c, int buf) {
        int i0 = c * 64;
        uint32_t stg = sb + buf * STAGE;
        #pragma unroll
        for (int it = 0; it < 4; ++it) {
            int idx = tid + it * 256;
            int row = idx >> 3, ch = idx & 7;
            const __half* src = A + (size_t)(m0 + row) * KDIM + i0 + ch * 8;
            CP_ASYNC16(stg + Ao + row * RS + ch * 16, src);
        }
        #pragma unroll
        for (int it = 0; it < BN / 32; ++it) {
            int idx = tid + it * 256;
            int row = idx >> 3, ch = idx & 7;
            const __half* src = W + (size_t)(n0 + row) * KDIM + i0 + ch * 8;
            CP_ASYNC16(stg + Bo + row * RS + ch * 16, src);
        }
        CP_COMMIT();
    };

    float acc[2][NT][4] = {};
    int g   = lane >> 2;
    int tig = lane & 3;
    int arow  = lane & 15;
    int acolb = (lane >> 4) * 16;
    int nrow  = (lane & 7) + ((lane >> 4) << 3);
    int bcolb = ((lane >> 3) & 1) * 16;

    load_chunk(0, 0);
    if (NC > 1) load_chunk(1, 1);

    int buf = 0;
    for (int c = 0; c < NC; ++c) {
        if (c + 1 < NC) CP_WAIT1(); else CP_WAIT0();
        __syncthreads();
        uint32_t stg = sb + buf * STAGE;
        #pragma unroll
        for (int kk = 0; kk < 4; ++kk) {
            uint32_t a_f[2][4];
            #pragma unroll
            for (int mt = 0; mt < 2; ++mt) {
                uint32_t ra = stg + Ao + (wy*32 + mt*16 + arow) * RS + kk*32 + acolb;
                LDSM4(a_f[mt], ra);
            }
            uint32_t b_f[P][4];
            #pragma unroll
            for (int p = 0; p < P; ++p) {
                uint32_t rb = stg + Bo + (wx*(BN/2) + p*16 + nrow) * RS + kk*32 + bcolb;
                LDSM4(b_f[p], rb);
            }
            #pragma unroll
            for (int mt = 0; mt < 2; ++mt)
                #pragma unroll
                for (int p = 0; p < P; ++p)
                    #pragma unroll
                    for (int h = 0; h < 2; ++h)
                        MMA16816H(acc[mt][p*2 + h], a_f[mt],
                                  b_f[p][h*2], b_f[p][h*2+1]);
        }
        if (c + 2 < NC) {
            int nb = buf + 2; if (nb >= 3) nb -= 3;
            load_chunk(c + 2, nb);
        }
        if (++buf >= 3) buf -= 3;
    }

    #pragma unroll
    for (int mt = 0; mt < 2; ++mt)
        #pragma unroll
        for (int nt = 0; nt < NT; ++nt) {
            int row = m0 + wy*32 + mt*16 + g;
            int col = n0 + wx*(BN/2) + nt*8 + tig*2;
            float* p0 = out + (size_t)row * N + col;
            atomicAdd(p0,     acc[mt][nt][0]);
            atomicAdd(p0 + 1, acc[mt][nt][1]);
            float* p1 = p0 + (size_t)8 * N;
            atomicAdd(p1,     acc[mt][nt][2]);
            atomicAdd(p1 + 1, acc[mt][nt][3]);
        }
}

// ===================== mma.sync expert GEMM (fp16, R14-frozen) =============
template<int IDIM, int BN, int NCTA>
__global__ __launch_bounds__(256, NCTA)
void expert_mma_kernel(const __half* __restrict__ Zf,
                       const __half* __restrict__ Wf,
                       const float* __restrict__ w,
                       const float* __restrict__ bias,
                       float* __restrict__ out,
                       int O, int eper) {
    constexpr int RS    = 144;
    constexpr int Ao    = 0;
    constexpr int Bo    = 128 * RS;
    constexpr int STAGE = (128 + BN) * RS;
    constexpr int CPE   = IDIM / 64;
    constexpr int P     = BN / 32;
    constexpr int NT    = BN / 16;

    __shared__ float wS[128 * 16];
    __shared__ float bS[16 * BN];
    extern __shared__ char smem[];
    uint32_t sb = smem_u32(smem);

    int tid  = threadIdx.x;
    int lane = tid & 31, wid = tid >> 5;
    int wy = wid >> 1, wx = wid & 1;
    int m0 = blockIdx.y * 128;
    int n0 = blockIdx.x * BN;
    int e0 = blockIdx.z * eper;
    const int nc = eper * CPE;

    {
        float inv = 1.f / g_sum;
        for (int i = tid; i < 128 * eper; i += 256) {
            int r = i / eper, el = i - r * eper;
            wS[r * 16 + el] = w[(size_t)(m0 + r) * NE + e0 + el] * inv;
        }
        for (int i = tid; i < eper * BN; i += 256) {
            int el = i / BN, col = i - el * BN;
            bS[el * BN + col] = bias[(size_t)(e0 + el) * O + n0 + col];
        }
    }

    auto load_chunk = [&](int c, int buf) {
        int e  = e0 + c / CPE;
        int i0 = (c % CPE) * 64;
        uint32_t stg = sb + buf * STAGE;
        #pragma unroll
        for (int it = 0; it < 4; ++it) {
            int idx = tid + it * 256;
            int row = idx >> 3, ch = idx & 7;
            const __half* src = Zf + (size_t)(m0 + row) * IDIM + i0 + ch * 8;
            CP_ASYNC16(stg + Ao + row * RS + ch * 16, src);
        }
        #pragma unroll
        for (int it = 0; it < BN / 32; ++it) {
            int idx = tid + it * 256;
            int row = idx >> 3, ch = idx & 7;
            const __half* src = Wf + ((size_t)e * O + n0 + row) * IDIM + i0 + ch * 8;
            CP_ASYNC16(stg + Bo + row * RS + ch * 16, src);
        }
        CP_COMMIT();
    };

    float accE[2][NT][4];
    float accO[2][NT][4] = {};
    int g   = lane >> 2;
    int tig = lane & 3;

    auto set_bias = [&](int el) {
        #pragma unroll
        for (int nt = 0; nt < NT; ++nt) {
            int col = wx * (BN / 2) + nt * 8 + tig * 2;
            float b0 = bS[el * BN + col];
            float b1 = bS[el * BN + col + 1];
            #pragma unroll
            for (int mt = 0; mt < 2; ++mt) {
                accE[mt][nt][0] = b0; accE[mt][nt][1] = b1;
                accE[mt][nt][2] = b0; accE[mt][nt][3] = b1;
            }
        }
    };

    int arow  = lane & 15;
    int acolb = (lane >> 4) * 16;
    int nrow  = (lane & 7) + ((lane >> 4) << 3);
    int bcolb = ((lane >> 3) & 1) * 16;

    load_chunk(0, 0);
    if (nc > 1) load_chunk(1, 1);
    __syncthreads();
    set_bias(0);

    int buf = 0;
    for (int c = 0; c < nc; ++c) {
        if (c + 1 < nc) CP_WAIT1(); else CP_WAIT0();
        __syncthreads();

        uint32_t stg = sb + buf * STAGE;
        #pragma unroll
        for (int kk = 0; kk < 4; ++kk) {
            uint32_t a_f[2][4];
            #pragma unroll
            for (int mt = 0; mt < 2; ++mt) {
                uint32_t ra = stg + Ao + (wy*32 + mt*16 + arow) * RS + kk*32 + acolb;
                LDSM4(a_f[mt], ra);
            }
            uint32_t b_f[P][4];
            #pragma unroll
            for (int p = 0; p < P; ++p) {
                uint32_t rb = stg + Bo + (wx*(BN/2) + p*16 + nrow) * RS + kk*32 + bcolb;
                LDSM4(b_f[p], rb);
            }
            #pragma unroll
            for (int mt = 0; mt < 2; ++mt)
                #pragma unroll
                for (int p = 0; p < P; ++p)
                    #pragma unroll
                    for (int h = 0; h < 2; ++h)
                        MMA16816H(accE[mt][p*2 + h], a_f[mt],
                                  b_f[p][h*2], b_f[p][h*2+1]);
        }

        if (c + 2 < nc) {
            int nb = buf + 2; if (nb >= 3) nb -= 3;
            load_chunk(c + 2, nb);
        }

        if (((c + 1) % CPE) == 0) {
            int el = c / CPE;
            float wv0[2], wv1[2];
            #pragma unroll
            for (int mt = 0; mt < 2; ++mt) {
                int r = wy*32 + mt*16 + g;
                wv0[mt] = wS[r * 16 + el];
                wv1[mt] = wS[(r + 8) * 16 + el];
            }
            #pragma unroll
            for (int mt = 0; mt < 2; ++mt)
                #pragma unroll
                for (int nt = 0; nt < NT; ++nt) {
                    accO[mt][nt][0] = fmaf(wv0[mt], accE[mt][nt][0], accO[mt][nt][0]);
                    accO[mt][nt][1] = fmaf(wv0[mt], accE[mt][nt][1], accO[mt][nt][1]);
                    accO[mt][nt][2] = fmaf(wv1[mt], accE[mt][nt][2], accO[mt][nt][2]);
                    accO[mt][nt][3] = fmaf(wv1[mt], accE[mt][nt][3], accO[mt][nt][3]);
                }
            if (c + 1 < nc) set_bias(el + 1);
        }

        if (++buf >= 3) buf -= 3;
    }

    #pragma unroll
    for (int mt = 0; mt < 2; ++mt)
        #pragma unroll
        for (int nt = 0; nt < NT; ++nt) {
            int row = m0 + wy*32 + mt*16 + g;
            int col = n0 + wx*(BN/2) + nt*8 + tig*2;
            float* p0 = out + (size_t)row * O + col;
            atomicAdd(p0,     accO[mt][nt][0]);
            atomicAdd(p0 + 1, accO[mt][nt][1]);
            float* p1 = p0 + (size_t)8 * O;
            atomicAdd(p1,     accO[mt][nt][2]);
            atomicAdd(p1 + 1, accO[mt][nt][3]);
        }
}

// ===========================================================================
extern "C" void kernel_launch(void* const* d_in, const int* in_sizes, int n_in,
                              void* d_out, int out_size) {
    const float* m0    = (const float*)d_in[0];
    const float* x0    = (const float*)d_in[1];
    const float* mW1   = (const float*)d_in[2];
    const float* mg1   = (const float*)d_in[4];
    const float* mbe1  = (const float*)d_in[5];
    const float* ma1   = (const float*)d_in[6];
    const float* mW2   = (const float*)d_in[7];
    const float* mg2   = (const float*)d_in[9];
    const float* mbe2  = (const float*)d_in[10];
    const float* ma2   = (const float*)d_in[11];
    const float* mW3   = (const float*)d_in[12];
    const float* mg3   = (const float*)d_in[14];
    const float* mbe3  = (const float*)d_in[15];
    const float* ma3   = (const float*)d_in[16];
    const float* Wenc0 = (const float*)d_in[17];
    const float* benc0 = (const float*)d_in[18];
    const float* Wenc1 = (const float*)d_in[19];
    const float* benc1 = (const float*)d_in[20];
    const float* Wdec0 = (const float*)d_in[21];
    const float* bdec0 = (const float*)d_in[22];
    const float* Wdec1 = (const float*)d_in[23];
    const float* bdec1 = (const float*)d_in[24];
    const float* bng   = (const float*)d_in[25];
    const float* bnb   = (const float*)d_in[26];
    const float* aP    = (const float*)d_in[27];
    float* out = (float*)d_out;

    float *b0, *b1, *b2, *wb, *sumP;
    __half *Wf, *Zf, *WmH, *WmL, *ZmH, *ZmL, *Zm2H, *Zm2L;
    cudaGetSymbolAddress((void**)&b0, g_buf0);
    cudaGetSymbolAddress((void**)&b1, g_buf1);
    cudaGetSymbolAddress((void**)&b2, g_buf2);
    cudaGetSymbolAddress((void**)&wb, g_w);
    cudaGetSymbolAddress((void**)&sumP, g_sum);
    cudaGetSymbolAddress((void**)&Wf, g_Wf);
    cudaGetSymbolAddress((void**)&Zf, g_Zf);
    cudaGetSymbolAddress((void**)&WmH, g_Wm);
    cudaGetSymbolAddress((void**)&WmL, g_Wml);
    cudaGetSymbolAddress((void**)&ZmH, g_Zm);
    cudaGetSymbolAddress((void**)&ZmL, g_Zml);
    cudaGetSymbolAddress((void**)&Zm2H, g_Zm2);
    cudaGetSymbolAddress((void**)&Zm2L, g_Zm2l);

    const int SMEM128 = 3 * (128 + 128) * 144;   // 110592
    const int SMEM64  = 3 * (128 +  64) * 144;   //  82944
    cudaFuncSetAttribute(expert_mma_kernel<64, 128, 1>,
                         cudaFuncAttributeMaxDynamicSharedMemorySize, SMEM128);
    cudaFuncSetAttribute(expert_mma_kernel<256, 128, 1>,
                         cudaFuncAttributeMaxDynamicSharedMemorySize, SMEM128);
    cudaFuncSetAttribute(expert_mma_kernel<256, 64, 1>,
                         cudaFuncAttributeMaxDynamicSharedMemorySize, SMEM64);
    cudaFuncSetAttribute(dense_mma_kernel<128, 128>,
                         cudaFuncAttributeMaxDynamicSharedMemorySize, SMEM128);
    cudaFuncSetAttribute(dense_mma_kernel<256, 128>,
                         cudaFuncAttributeMaxDynamicSharedMemorySize, SMEM128);
    cudaFuncSetAttribute(dense_mma_kernel<128, 64>,
                         cudaFuncAttributeMaxDynamicSharedMemorySize, SMEM64);

    // ---- convert everything (one kernel) ----
    cvt_all_kernel<<<N8_8 / 256, 256>>>(Wenc0, Wenc1, Wdec0, Wdec1, x0,
                                        mW1, mW2, mW3, m0,
                                        Wf, Zf, WmH, WmL, ZmH, ZmL);

    // ---- MNet: 3x (3-product hi/lo tensor GEMM -> BN -> PReLU) ----
    cudaMemsetAsync(b0, 0, BATCH * 256 * sizeof(float));
    dense_mma_kernel<128, 128><<<dim3(2, 32, 3), 256, SMEM128>>>(
        ZmH, ZmL, WmH + OFF_MW1, WmL + OFF_MW1, b0, 256);
    bn_prelu_hl_kernel<<<128, 256>>>(b0, mg1, mbe1, ma1, 256, Zm2H, Zm2L);
    cudaMemsetAsync(b1, 0, BATCH * 128 * sizeof(float));
    dense_mma_kernel<256, 128><<<dim3(1, 32, 3), 256, SMEM128>>>(
        Zm2H, Zm2L, WmH + OFF_MW2, WmL + OFF_MW2, b1, 128);
    bn_prelu_hl_kernel<<<64, 256>>>(b1, mg2, mbe2, ma2, 128, ZmH, ZmL);
    cudaMemsetAsync(wb, 0, BATCH * 64 * sizeof(float));
    dense_mma_kernel<128, 64><<<dim3(1, 32, 3), 256, SMEM64>>>(
        ZmH, ZmL, WmH + OFF_MW3, WmL + OFF_MW3, wb, 64);
    cudaMemsetAsync(sumP, 0, sizeof(float));
    bn_prelu_wsum_kernel<<<32, 256>>>(wb, mg3, mbe3, ma3, 64);

    // ---- encoder layer 0: x0[4096,64] -> b2[4096,256] ----
    cudaMemsetAsync(b2, 0, BATCH * 256 * sizeof(float));
    expert_mma_kernel<64, 128, 1><<<dim3(2, 32, 4), 256, SMEM128>>>(
        Zf, Wf + OFF_ENC0, wb, benc0, b2, 256, 16);
    bn_prelu_h_kernel<<<128, 256>>>(b2, bng, bnb, aP, 256, Zf);

    // ---- encoder layer 1: -> b0 ----
    cudaMemsetAsync(b0, 0, BATCH * 256 * sizeof(float));
    expert_mma_kernel<256, 128, 1><<<dim3(2, 32, 4), 256, SMEM128>>>(
        Zf, Wf + OFF_ENC1, wb, benc1, b0, 256, 16);
    bn_prelu_h_kernel<<<128, 256>>>(b0, bng, bnb, aP, 256, Zf);

    // ---- decoder layer 0: -> b1 ----
    cudaMemsetAsync(b1, 0, BATCH * 256 * sizeof(float));
    expert_mma_kernel<256, 128, 1><<<dim3(2, 32, 4), 256, SMEM128>>>(
        Zf, Wf + OFF_DEC0, wb, bdec0, b1, 256, 16);
    bn_prelu_h_kernel<<<128, 256>>>(b1, bng, bnb, aP, 256, Zf);

    // ---- decoder layer 1 (no BN/PReLU): -> out [4096,64] ----
    cudaMemsetAsync(out, 0, BATCH * 64 * sizeof(float));
    expert_mma_kernel<256, 64, 1><<<dim3(1, 32, 8), 256, SMEM64>>>(
        Zf, Wf + OFF_DEC1, wb, bdec1, out, 64, 8);
}